// round 1
// baseline (speedup 1.0000x reference)
#include <cuda_runtime.h>

#define NE   50000
#define NRL  64
#define NT   400000
#define D    128
#define NH   8

// ---------------- scratch (device globals; no allocation) ----------------
__device__ float g_P1[NE * D];      // emb_ent @ Wa[0:128]   (tail part)
__device__ float g_P2[NE * D];      // emb_ent @ Wa[128:256] (head part)
__device__ float g_G1[NE * D];      // emb_ent @ Wg[0:128]   (head part of msg)
__device__ float g_SM[NE * D];      // self-edge message: G1 + Sg + bg
__device__ float g_selfA[NE * NH];  // self-edge attn_raw per head
__device__ float g_AR[NT * NH];     // per-triplet attn_raw per head
__device__ float g_hist[NE * NRL];  // per-entity relation histogram (counts)
__device__ float g_Ra[NRL * D];     // emb_rel @ Wa[256:384]
__device__ float g_Rg[NRL * D];     // emb_rel @ Wg[128:256]
__device__ int   g_off[NE + 1];
__device__ int   g_cur[NE];
__device__ int   g_deg[NE];
__device__ int   g_eidx[NT];

__device__ __forceinline__ float tanh_fast(float x) {
    // 1 - 2/(e^{2x}+1); correct saturation at +-inf, abs err ~1e-7
    float e = __expf(2.0f * x);
    return 1.0f - 2.0f / (e + 1.0f);
}

// ---------------- K0: zero hist + cursors ----------------
__global__ void k_zero() {
    int i = blockIdx.x * blockDim.x + threadIdx.x;
    int stride = gridDim.x * blockDim.x;
    for (int t = i; t < NE * NRL; t += stride) g_hist[t] = 0.0f;
    for (int t = i; t < NE; t += stride) g_cur[t] = 0;
}

// ---------------- K1: relation histogram ----------------
__global__ void k_hist(const int* __restrict__ trip) {
    int i = blockIdx.x * blockDim.x + threadIdx.x;
    if (i < NT) {
        int rl = trip[i * 3 + 1];
        int tl = trip[i * 3 + 2];
        atomicAdd(&g_hist[tl * NRL + rl], 1.0f);
    }
}

// ---------------- K2: Ra, Rg (64 x 128 each) ----------------
__global__ void k_rel(const float* __restrict__ emb_rel,
                      const float* __restrict__ Wa,
                      const float* __restrict__ Wg) {
    __shared__ float x[D];
    int r = blockIdx.x;
    int j = threadIdx.x;
    x[j] = emb_rel[r * D + j];
    __syncthreads();
    float ra = 0.0f, rg = 0.0f;
    #pragma unroll 8
    for (int k = 0; k < D; k++) {
        float xv = x[k];
        ra = fmaf(xv, Wa[(256 + k) * D + j], ra);
        rg = fmaf(xv, Wg[(128 + k) * D + j], rg);
    }
    g_Ra[r * D + j] = ra;
    g_Rg[r * D + j] = rg;
}

// ---------------- K3: per-entity GEMM  C(50000x128) = X @ W  (3 weight mats) --
// 128x128 output tile per block, K=128, 256 threads, 8x8 micro-tile per thread.
__global__ __launch_bounds__(256) void k_ent(const float* __restrict__ X,
                                             const float* __restrict__ Wa,
                                             const float* __restrict__ Wg) {
    __shared__ float Xs[16][128];  // [k][m]
    __shared__ float Ws[16][128];  // [k][j]
    int tid = threadIdx.x;
    int tx = tid & 15;
    int ty = tid >> 4;
    int m_base = blockIdx.x * 128;

    const float* Wsrc[3] = { Wa, Wa + 128 * D, Wg };
    float* Cdst[3] = { g_P1, g_P2, g_G1 };

    for (int w = 0; w < 3; ++w) {
        float acc[2][2][4][4];
        #pragma unroll
        for (int a = 0; a < 2; a++)
            #pragma unroll
            for (int b = 0; b < 2; b++)
                #pragma unroll
                for (int i = 0; i < 4; i++)
                    #pragma unroll
                    for (int jj = 0; jj < 4; jj++) acc[a][b][i][jj] = 0.0f;

        const float* Wp = Wsrc[w];
        for (int kb = 0; kb < D; kb += 16) {
            // load X tile transposed: Xs[kk][m]
            {
                int m  = tid >> 1;
                int k4 = (tid & 1) * 8;
                int gm = m_base + m;
                float4 v0 = make_float4(0, 0, 0, 0), v1 = make_float4(0, 0, 0, 0);
                if (gm < NE) {
                    v0 = *(const float4*)&X[gm * D + kb + k4];
                    v1 = *(const float4*)&X[gm * D + kb + k4 + 4];
                }
                Xs[k4 + 0][m] = v0.x; Xs[k4 + 1][m] = v0.y;
                Xs[k4 + 2][m] = v0.z; Xs[k4 + 3][m] = v0.w;
                Xs[k4 + 4][m] = v1.x; Xs[k4 + 5][m] = v1.y;
                Xs[k4 + 6][m] = v1.z; Xs[k4 + 7][m] = v1.w;
            }
            // load W tile: Ws[kk][j]
            {
                int r  = tid >> 5;
                int c4 = (tid & 31) * 4;
                *(float4*)&Ws[r][c4]     = *(const float4*)&Wp[(kb + r) * D + c4];
                *(float4*)&Ws[r + 8][c4] = *(const float4*)&Wp[(kb + r + 8) * D + c4];
            }
            __syncthreads();
            #pragma unroll
            for (int kk = 0; kk < 16; ++kk) {
                float4 x0 = *(float4*)&Xs[kk][ty * 4];
                float4 x1 = *(float4*)&Xs[kk][64 + ty * 4];
                float4 w0 = *(float4*)&Ws[kk][tx * 4];
                float4 w1 = *(float4*)&Ws[kk][64 + tx * 4];
                float xa[2][4] = { {x0.x, x0.y, x0.z, x0.w}, {x1.x, x1.y, x1.z, x1.w} };
                float wb[2][4] = { {w0.x, w0.y, w0.z, w0.w}, {w1.x, w1.y, w1.z, w1.w} };
                #pragma unroll
                for (int a = 0; a < 2; a++)
                    #pragma unroll
                    for (int i = 0; i < 4; i++)
                        #pragma unroll
                        for (int b = 0; b < 2; b++)
                            #pragma unroll
                            for (int jj = 0; jj < 4; jj++)
                                acc[a][b][i][jj] = fmaf(xa[a][i], wb[b][jj], acc[a][b][i][jj]);
            }
            __syncthreads();
        }
        float* C = Cdst[w];
        #pragma unroll
        for (int a = 0; a < 2; a++)
            #pragma unroll
            for (int i = 0; i < 4; i++) {
                int gm = m_base + a * 64 + ty * 4 + i;
                if (gm < NE) {
                    #pragma unroll
                    for (int b = 0; b < 2; b++) {
                        float4 v = make_float4(acc[a][b][i][0], acc[a][b][i][1],
                                               acc[a][b][i][2], acc[a][b][i][3]);
                        *(float4*)&C[gm * D + b * 64 + tx * 4] = v;
                    }
                }
            }
    }
}

// ---------------- K4: self-edge message + self attention + degree ----------
__global__ void k_self(const float* __restrict__ ba,
                       const float* __restrict__ bg,
                       const float* __restrict__ av) {
    int e = blockIdx.x;
    int j = threadIdx.x;  // 128
    __shared__ float h[NRL];
    if (j < NRL) h[j] = g_hist[e * NRL + j];
    __syncthreads();

    float cnt = 0.0f;
    #pragma unroll
    for (int r = 0; r < NRL; r++) cnt += h[r];

    float sa = 0.0f, sg = 0.0f;
    #pragma unroll 8
    for (int r = 0; r < NRL; r++) {
        float hv = h[r];
        sa = fmaf(hv, g_Ra[r * D + j], sa);
        sg = fmaf(hv, g_Rg[r * D + j], sg);
    }
    float inv = (cnt > 0.0f) ? (1.0f / cnt) : 0.0f;

    g_SM[e * D + j] = g_G1[e * D + j] + sg * inv + bg[j];

    float hval = tanh_fast(g_P1[e * D + j] + g_P2[e * D + j] + sa * inv + ba[j]);
    float prod = hval * av[j];
    // reduce within 16-lane head groups
    #pragma unroll
    for (int o = 8; o > 0; o >>= 1)
        prod += __shfl_down_sync(0xffffffffu, prod, o, 16);
    if ((j & 15) == 0) g_selfA[e * NH + (j >> 4)] = prod;
    if (j == 0) g_deg[e] = (int)(cnt + 0.5f);
}

// ---------------- K5: per-triplet attention raw scores ----------------
__global__ void k_edge(const int* __restrict__ trip,
                       const float* __restrict__ ba,
                       const float* __restrict__ av) {
    int idx = blockIdx.x * blockDim.x + threadIdx.x;
    int edge = idx >> 5;
    int lane = idx & 31;
    if (edge >= NT) return;
    int hd = trip[edge * 3 + 0];
    int rl = trip[edge * 3 + 1];
    int tl = trip[edge * 3 + 2];
    int j = lane * 4;
    float4 p1 = *(const float4*)&g_P1[tl * D + j];
    float4 p2 = *(const float4*)&g_P2[hd * D + j];
    float4 ra = *(const float4*)&g_Ra[rl * D + j];
    float4 b  = *(const float4*)&ba[j];
    float4 a  = *(const float4*)&av[j];
    float s = 0.0f;
    s = fmaf(tanh_fast(p1.x + p2.x + ra.x + b.x), a.x, s);
    s = fmaf(tanh_fast(p1.y + p2.y + ra.y + b.y), a.y, s);
    s = fmaf(tanh_fast(p1.z + p2.z + ra.z + b.z), a.z, s);
    s = fmaf(tanh_fast(p1.w + p2.w + ra.w + b.w), a.w, s);
    // reduce across the 4 lanes of one head (j spans 16 per head)
    s += __shfl_xor_sync(0xffffffffu, s, 1);
    s += __shfl_xor_sync(0xffffffffu, s, 2);
    if ((lane & 3) == 0) g_AR[edge * NH + (lane >> 2)] = s;
}

// ---------------- K6: exclusive prefix scan of degrees (single block) ------
__global__ void k_scan() {
    __shared__ int s[1024];
    int t = threadIdx.x;
    const int CH = (NE + 1023) / 1024;  // 49
    int base = t * CH;
    int sum = 0;
    for (int i = 0; i < CH; i++)
        if (base + i < NE) sum += g_deg[base + i];
    s[t] = sum;
    __syncthreads();
    for (int o = 1; o < 1024; o <<= 1) {
        int v = (t >= o) ? s[t - o] : 0;
        __syncthreads();
        s[t] += v;
        __syncthreads();
    }
    int run = (t > 0) ? s[t - 1] : 0;
    for (int i = 0; i < CH; i++) {
        if (base + i < NE) {
            g_off[base + i] = run;
            run += g_deg[base + i];
        }
    }
    if (t == 1023) g_off[NE] = s[1023];
}

// ---------------- K7: scatter edge ids into CSR ----------------
__global__ void k_scatter(const int* __restrict__ trip) {
    int i = blockIdx.x * blockDim.x + threadIdx.x;
    if (i < NT) {
        int tl = trip[i * 3 + 2];
        int p = atomicAdd(&g_cur[tl], 1);
        g_eidx[g_off[tl] + p] = i;
    }
}

// ---------------- K8: per-entity softmax + aggregation (1 warp/entity) -----
__global__ void k_gather(const int* __restrict__ trip,
                         const float* __restrict__ bg,
                         float* __restrict__ out) {
    int wg = (blockIdx.x * blockDim.x + threadIdx.x) >> 5;
    int lane = threadIdx.x & 31;
    if (wg >= NE) return;
    int e = wg;
    int o0 = g_off[e], o1 = g_off[e + 1];
    int deg = o1 - o0;

    // pass 1: per-head max (lane handles head lane&7, strided over edges)
    int h8 = lane & 7;
    float m = g_selfA[e * NH + h8];
    for (int jj = lane >> 3; jj < deg; jj += 4) {
        int ei = g_eidx[o0 + jj];
        m = fmaxf(m, g_AR[ei * NH + h8]);
    }
    m = fmaxf(m, __shfl_xor_sync(0xffffffffu, m, 8));
    m = fmaxf(m, __shfl_xor_sync(0xffffffffu, m, 16));
    int hh = lane >> 2;                              // head for this lane's 4 outputs
    float amax = __shfl_sync(0xffffffffu, m, hh);    // lane hh holds head hh's max

    int j = lane * 4;
    float4 bgv = *(const float4*)&bg[j];
    float ax = 0.0f, ay = 0.0f, az = 0.0f, aw = 0.0f;
    float denom = 0.0f;

    // self edge (SM already includes bg)
    {
        float a = g_selfA[e * NH + hh];
        float ev = __expf(a - amax);
        float4 mm = *(const float4*)&g_SM[e * D + j];
        ax = fmaf(ev, mm.x, ax); ay = fmaf(ev, mm.y, ay);
        az = fmaf(ev, mm.z, az); aw = fmaf(ev, mm.w, aw);
        denom += ev;
    }
    for (int jj = 0; jj < deg; ++jj) {
        int ei = g_eidx[o0 + jj];
        int hd = trip[ei * 3 + 0];
        int rl = trip[ei * 3 + 1];
        float a = g_AR[ei * NH + hh];
        float ev = __expf(a - amax);
        float4 g = *(const float4*)&g_G1[hd * D + j];
        float4 r = *(const float4*)&g_Rg[rl * D + j];
        ax = fmaf(ev, g.x + r.x + bgv.x, ax);
        ay = fmaf(ev, g.y + r.y + bgv.y, ay);
        az = fmaf(ev, g.z + r.z + bgv.z, az);
        aw = fmaf(ev, g.w + r.w + bgv.w, aw);
        denom += ev;
    }
    float inv = 1.0f / denom;
    float4 o = make_float4(ax * inv, ay * inv, az * inv, aw * inv);
    *(float4*)&out[e * D + j] = o;
}

// ---------------- launch ----------------
extern "C" void kernel_launch(void* const* d_in, const int* in_sizes, int n_in,
                              void* d_out, int out_size) {
    const float* emb_ent = (const float*)d_in[0];
    const float* emb_rel = (const float*)d_in[1];
    const int*   trip    = (const int*)d_in[2];
    const float* Wa      = (const float*)d_in[3];
    const float* ba      = (const float*)d_in[4];
    const float* av      = (const float*)d_in[5];
    const float* Wg      = (const float*)d_in[6];
    const float* bg      = (const float*)d_in[7];
    float* out = (float*)d_out;

    k_zero<<<4096, 256>>>();
    k_hist<<<(NT + 255) / 256, 256>>>(trip);
    k_rel<<<NRL, 128>>>(emb_rel, Wa, Wg);
    k_ent<<<(NE + 127) / 128, 256>>>(emb_ent, Wa, Wg);
    k_self<<<NE, 128>>>(ba, bg, av);
    k_edge<<<(NT * 32 + 255) / 256, 256>>>(trip, ba, av);
    k_scan<<<1, 1024>>>();
    k_scatter<<<(NT + 255) / 256, 256>>>(trip);
    k_gather<<<(NE * 32 + 255) / 256, 256>>>(trip, bg, out);
}

// round 3
// speedup vs baseline: 1.9765x; 1.9765x over previous
#include <cuda_runtime.h>

#define NE   50000
#define NRL  64
#define NT   400000
#define D    128
#define NH   8

// ---------------- scratch (device globals; no allocation) ----------------
__device__ float g_P1[NE * D];      // emb_ent @ Wa[0:128]   (tail part)
__device__ float g_P2[NE * D];      // emb_ent @ Wa[128:256] (head part)
__device__ float g_G1[NE * D];      // emb_ent @ Wg[0:128]   (head part of msg)
__device__ float g_Ra[NRL * D];     // emb_rel @ Wa[256:384]
__device__ float g_Rg[NRL * D];     // emb_rel @ Wg[128:256]
__device__ int   g_off[NE + 1];
__device__ int   g_cur[NE];
__device__ int   g_deg[NE];
__device__ int2  g_ehr[NT];         // CSR payload: (head, rel) per edge, grouped by tail

// ---------------- helpers ----------------
__device__ __forceinline__ float tanh_fast(float x) {
    float y;
    asm("tanh.approx.f32 %0, %1;" : "=f"(y) : "f"(x));
    return y;
}
__device__ __forceinline__ unsigned long long dup2(float x) {
    unsigned long long r;
    asm("mov.b64 %0, {%1, %1};" : "=l"(r) : "f"(x));
    return r;
}
__device__ __forceinline__ unsigned long long ffma2(unsigned long long a,
                                                    unsigned long long b,
                                                    unsigned long long c) {
    unsigned long long d;
    asm("fma.rn.f32x2 %0, %1, %2, %3;" : "=l"(d) : "l"(a), "l"(b), "l"(c));
    return d;
}

// ---------------- K0: zero deg + cursors ----------------
__global__ void k_zero() {
    int i = blockIdx.x * blockDim.x + threadIdx.x;
    if (i < NE) { g_deg[i] = 0; g_cur[i] = 0; }
}

// ---------------- K1: degree count ----------------
__global__ void k_count(const int* __restrict__ trip) {
    int i = blockIdx.x * blockDim.x + threadIdx.x;
    if (i < NT) atomicAdd(&g_deg[trip[i * 3 + 2]], 1);
}

// ---------------- K2: Ra, Rg (64 x 128 each) ----------------
__global__ void k_rel(const float* __restrict__ emb_rel,
                      const float* __restrict__ Wa,
                      const float* __restrict__ Wg) {
    __shared__ float x[D];
    int r = blockIdx.x;
    int j = threadIdx.x;
    x[j] = emb_rel[r * D + j];
    __syncthreads();
    float ra = 0.0f, rg = 0.0f;
    #pragma unroll 8
    for (int k = 0; k < D; k++) {
        float xv = x[k];
        ra = fmaf(xv, Wa[(256 + k) * D + j], ra);
        rg = fmaf(xv, Wg[(128 + k) * D + j], rg);
    }
    g_Ra[r * D + j] = ra;
    g_Rg[r * D + j] = rg;
}

// ---------------- K3: per-entity GEMM via packed fma.rn.f32x2 ----------------
// C(50000x128) = X @ W; blockIdx.y picks one of 3 weight matrices.
// 128x128 tile / block, 256 threads, 8x8 micro-tile (4 f32x2 col-pairs).
__global__ __launch_bounds__(256) void k_ent(const float* __restrict__ X,
                                             const float* __restrict__ Wa,
                                             const float* __restrict__ Wg) {
    __shared__ __align__(16) float Xs[16][128];  // [k][m]
    __shared__ __align__(16) float Ws[16][128];  // [k][j]
    int tid = threadIdx.x;
    int tx = tid & 15;
    int ty = tid >> 4;
    int m_base = blockIdx.x * 128;
    int w = blockIdx.y;

    const float* Wp = (w == 0) ? Wa : (w == 1) ? (Wa + 128 * D) : Wg;
    float* C = (w == 0) ? g_P1 : (w == 1) ? g_P2 : g_G1;

    unsigned long long acc[2][2][4][2];
    #pragma unroll
    for (int a = 0; a < 2; a++)
        #pragma unroll
        for (int b = 0; b < 2; b++)
            #pragma unroll
            for (int i = 0; i < 4; i++) {
                acc[a][b][i][0] = 0ULL;
                acc[a][b][i][1] = 0ULL;
            }

    for (int kb = 0; kb < D; kb += 16) {
        // load X tile transposed: Xs[kk][m]
        {
            int m  = tid >> 1;
            int k4 = (tid & 1) * 8;
            int gm = m_base + m;
            float4 v0 = make_float4(0, 0, 0, 0), v1 = make_float4(0, 0, 0, 0);
            if (gm < NE) {
                v0 = *(const float4*)&X[gm * D + kb + k4];
                v1 = *(const float4*)&X[gm * D + kb + k4 + 4];
            }
            Xs[k4 + 0][m] = v0.x; Xs[k4 + 1][m] = v0.y;
            Xs[k4 + 2][m] = v0.z; Xs[k4 + 3][m] = v0.w;
            Xs[k4 + 4][m] = v1.x; Xs[k4 + 5][m] = v1.y;
            Xs[k4 + 6][m] = v1.z; Xs[k4 + 7][m] = v1.w;
        }
        // load W tile: Ws[kk][j]
        {
            int r  = tid >> 5;
            int c4 = (tid & 31) * 4;
            *(float4*)&Ws[r][c4]     = *(const float4*)&Wp[(kb + r) * D + c4];
            *(float4*)&Ws[r + 8][c4] = *(const float4*)&Wp[(kb + r + 8) * D + c4];
        }
        __syncthreads();
        #pragma unroll
        for (int kk = 0; kk < 16; ++kk) {
            float4 x0 = *(float4*)&Xs[kk][ty * 4];         // broadcast across tx
            float4 x1 = *(float4*)&Xs[kk][64 + ty * 4];
            const unsigned long long* wr = (const unsigned long long*)&Ws[kk][0];
            // Ws row = 128 floats = 64 ulls; columns 64.. start at ull index 32.
            unsigned long long w00 = wr[tx * 2];
            unsigned long long w01 = wr[tx * 2 + 1];
            unsigned long long w10 = wr[32 + tx * 2];
            unsigned long long w11 = wr[32 + tx * 2 + 1];

            unsigned long long xd[2][4];
            xd[0][0] = dup2(x0.x); xd[0][1] = dup2(x0.y);
            xd[0][2] = dup2(x0.z); xd[0][3] = dup2(x0.w);
            xd[1][0] = dup2(x1.x); xd[1][1] = dup2(x1.y);
            xd[1][2] = dup2(x1.z); xd[1][3] = dup2(x1.w);

            #pragma unroll
            for (int a = 0; a < 2; a++)
                #pragma unroll
                for (int i = 0; i < 4; i++) {
                    acc[a][0][i][0] = ffma2(xd[a][i], w00, acc[a][0][i][0]);
                    acc[a][0][i][1] = ffma2(xd[a][i], w01, acc[a][0][i][1]);
                    acc[a][1][i][0] = ffma2(xd[a][i], w10, acc[a][1][i][0]);
                    acc[a][1][i][1] = ffma2(xd[a][i], w11, acc[a][1][i][1]);
                }
        }
        __syncthreads();
    }
    #pragma unroll
    for (int a = 0; a < 2; a++)
        #pragma unroll
        for (int i = 0; i < 4; i++) {
            int gm = m_base + a * 64 + ty * 4 + i;
            if (gm < NE) {
                #pragma unroll
                for (int b = 0; b < 2; b++) {
                    uint2 lo = *reinterpret_cast<uint2*>(&acc[a][b][i][0]);
                    uint2 hi = *reinterpret_cast<uint2*>(&acc[a][b][i][1]);
                    float4 v = make_float4(__uint_as_float(lo.x), __uint_as_float(lo.y),
                                           __uint_as_float(hi.x), __uint_as_float(hi.y));
                    *(float4*)&C[gm * D + b * 64 + tx * 4] = v;
                }
            }
        }
}

// ---------------- K4: exclusive prefix scan of degrees (single block) ------
__global__ void k_scan() {
    __shared__ int s[1024];
    int t = threadIdx.x;
    const int CH = (NE + 1023) / 1024;  // 49
    int base = t * CH;
    int sum = 0;
    for (int i = 0; i < CH; i++)
        if (base + i < NE) sum += g_deg[base + i];
    s[t] = sum;
    __syncthreads();
    for (int o = 1; o < 1024; o <<= 1) {
        int v = (t >= o) ? s[t - o] : 0;
        __syncthreads();
        s[t] += v;
        __syncthreads();
    }
    int run = (t > 0) ? s[t - 1] : 0;
    for (int i = 0; i < CH; i++) {
        if (base + i < NE) {
            g_off[base + i] = run;
            run += g_deg[base + i];
        }
    }
    if (t == 1023) g_off[NE] = s[1023];
}

// ---------------- K5: scatter (head, rel) into CSR ----------------
__global__ void k_scatter(const int* __restrict__ trip) {
    int i = blockIdx.x * blockDim.x + threadIdx.x;
    if (i < NT) {
        int hd = trip[i * 3 + 0];
        int rl = trip[i * 3 + 1];
        int tl = trip[i * 3 + 2];
        int p = atomicAdd(&g_cur[tl], 1);
        g_ehr[g_off[tl] + p] = make_int2(hd, rl);
    }
}

// ---------------- K6: fused attention + softmax + aggregation -------------
// 1 warp per entity. No max-subtraction: |attn_raw| <= sum|av| ~ 1.5, exp safe,
// softmax is shift-invariant so result is identical.
__global__ __launch_bounds__(256) void k_gather(const float* __restrict__ ba,
                                                const float* __restrict__ bg,
                                                const float* __restrict__ av,
                                                float* __restrict__ out) {
    int e = (blockIdx.x * blockDim.x + threadIdx.x) >> 5;
    int lane = threadIdx.x & 31;
    if (e >= NE) return;
    int o0 = g_off[e];
    int deg = g_off[e + 1] - o0;

    int j = lane * 4;
    float4 p1  = *(const float4*)&g_P1[e * D + j];
    float4 bav = *(const float4*)&ba[j];
    float4 av4 = *(const float4*)&av[j];
    float4 bg4 = *(const float4*)&bg[j];
    // p1 + ba precombined
    p1.x += bav.x; p1.y += bav.y; p1.z += bav.z; p1.w += bav.w;

    float ax = 0.f, ay = 0.f, az = 0.f, aw = 0.f;  // weighted msg accum
    float denom = 0.f;
    float sax = 0.f, say = 0.f, saz = 0.f, saw = 0.f;  // sum Ra[rel]
    float sgx = 0.f, sgy = 0.f, sgz = 0.f, sgw = 0.f;  // sum Rg[rel]

    for (int jj = 0; jj < deg; ++jj) {
        int2 hr = g_ehr[o0 + jj];
        float4 p2 = *(const float4*)&g_P2[hr.x * D + j];
        float4 ra = *(const float4*)&g_Ra[hr.y * D + j];
        float4 g1 = *(const float4*)&g_G1[hr.x * D + j];
        float4 rg = *(const float4*)&g_Rg[hr.y * D + j];

        float s = 0.f;
        s = fmaf(tanh_fast(p1.x + p2.x + ra.x), av4.x, s);
        s = fmaf(tanh_fast(p1.y + p2.y + ra.y), av4.y, s);
        s = fmaf(tanh_fast(p1.z + p2.z + ra.z), av4.z, s);
        s = fmaf(tanh_fast(p1.w + p2.w + ra.w), av4.w, s);
        // reduce within 4-lane head group -> every lane holds its head's score
        s += __shfl_xor_sync(0xffffffffu, s, 1);
        s += __shfl_xor_sync(0xffffffffu, s, 2);
        float ev = __expf(s);

        ax = fmaf(ev, g1.x + rg.x + bg4.x, ax);
        ay = fmaf(ev, g1.y + rg.y + bg4.y, ay);
        az = fmaf(ev, g1.z + rg.z + bg4.z, az);
        aw = fmaf(ev, g1.w + rg.w + bg4.w, aw);
        denom += ev;

        sax += ra.x; say += ra.y; saz += ra.z; saw += ra.w;
        sgx += rg.x; sgy += rg.y; sgz += rg.z; sgw += rg.w;
    }

    // ---- self edge: head = e, rel-feat = mean of Ra/Rg over incoming edges
    {
        float inv = (deg > 0) ? (1.0f / (float)deg) : 0.0f;
        float4 p2 = *(const float4*)&g_P2[e * D + j];
        float4 g1 = *(const float4*)&g_G1[e * D + j];
        float s = 0.f;
        s = fmaf(tanh_fast(p1.x + p2.x + sax * inv), av4.x, s);
        s = fmaf(tanh_fast(p1.y + p2.y + say * inv), av4.y, s);
        s = fmaf(tanh_fast(p1.z + p2.z + saz * inv), av4.z, s);
        s = fmaf(tanh_fast(p1.w + p2.w + saw * inv), av4.w, s);
        s += __shfl_xor_sync(0xffffffffu, s, 1);
        s += __shfl_xor_sync(0xffffffffu, s, 2);
        float ev = __expf(s);
        ax = fmaf(ev, g1.x + sgx * inv + bg4.x, ax);
        ay = fmaf(ev, g1.y + sgy * inv + bg4.y, ay);
        az = fmaf(ev, g1.z + sgz * inv + bg4.z, az);
        aw = fmaf(ev, g1.w + sgw * inv + bg4.w, aw);
        denom += ev;
    }

    float inv = 1.0f / denom;
    *(float4*)&out[e * D + j] = make_float4(ax * inv, ay * inv, az * inv, aw * inv);
}

// ---------------- launch ----------------
extern "C" void kernel_launch(void* const* d_in, const int* in_sizes, int n_in,
                              void* d_out, int out_size) {
    const float* emb_ent = (const float*)d_in[0];
    const float* emb_rel = (const float*)d_in[1];
    const int*   trip    = (const int*)d_in[2];
    const float* Wa      = (const float*)d_in[3];
    const float* ba      = (const float*)d_in[4];
    const float* av      = (const float*)d_in[5];
    const float* Wg      = (const float*)d_in[6];
    const float* bg      = (const float*)d_in[7];
    float* out = (float*)d_out;

    k_zero<<<(NE + 255) / 256, 256>>>();
    k_count<<<(NT + 255) / 256, 256>>>(trip);
    k_rel<<<NRL, 128>>>(emb_rel, Wa, Wg);
    dim3 ent_grid((NE + 127) / 128, 3);
    k_ent<<<ent_grid, 256>>>(emb_ent, Wa, Wg);
    k_scan<<<1, 1024>>>();
    k_scatter<<<(NT + 255) / 256, 256>>>(trip);
    k_gather<<<(NE * 32 + 255) / 256, 256>>>(ba, bg, av, out);
}

// round 4
// speedup vs baseline: 2.0249x; 1.0245x over previous
#include <cuda_runtime.h>

#define NE   50000
#define NRL  64
#define NT   400000
#define D    128
#define NH   8

// ---------------- scratch (device globals; no allocation) ----------------
__device__ float g_P1[NE * D];      // emb_ent @ Wa[0:128]   (tail part)
__device__ float g_P2[NE * D];      // emb_ent @ Wa[128:256] (head part)
__device__ float g_G1[NE * D];      // emb_ent @ Wg[0:128]   (head part of msg)
__device__ float g_Ra[NRL * D];     // emb_rel @ Wa[256:384]
__device__ float g_Rg[NRL * D];     // emb_rel @ Wg[128:256]
__device__ int   g_off[NE + 1];
__device__ int   g_cur[NE];
__device__ int   g_deg[NE];
__device__ int2  g_ehr[NT];         // CSR payload: (head, rel) per edge, grouped by tail

// ---------------- helpers ----------------
__device__ __forceinline__ float tanh_fast(float x) {
    float y;
    asm("tanh.approx.f32 %0, %1;" : "=f"(y) : "f"(x));
    return y;
}
__device__ __forceinline__ unsigned long long dup2(float x) {
    unsigned long long r;
    asm("mov.b64 %0, {%1, %1};" : "=l"(r) : "f"(x));
    return r;
}
__device__ __forceinline__ unsigned long long ffma2(unsigned long long a,
                                                    unsigned long long b,
                                                    unsigned long long c) {
    unsigned long long d;
    asm("fma.rn.f32x2 %0, %1, %2, %3;" : "=l"(d) : "l"(a), "l"(b), "l"(c));
    return d;
}

// ---------------- K0: zero deg + cursors ----------------
__global__ void k_zero() {
    int i = blockIdx.x * blockDim.x + threadIdx.x;
    if (i < NE) { g_deg[i] = 0; g_cur[i] = 0; }
}

// ---------------- K1: degree count ----------------
__global__ void k_count(const int* __restrict__ trip) {
    int i = blockIdx.x * blockDim.x + threadIdx.x;
    if (i < NT) atomicAdd(&g_deg[trip[i * 3 + 2]], 1);
}

// ---------------- K2: Ra, Rg (64 x 128 each) ----------------
__global__ void k_rel(const float* __restrict__ emb_rel,
                      const float* __restrict__ Wa,
                      const float* __restrict__ Wg) {
    __shared__ float x[D];
    int r = blockIdx.x;
    int j = threadIdx.x;
    x[j] = emb_rel[r * D + j];
    __syncthreads();
    float ra = 0.0f, rg = 0.0f;
    #pragma unroll 8
    for (int k = 0; k < D; k++) {
        float xv = x[k];
        ra = fmaf(xv, Wa[(256 + k) * D + j], ra);
        rg = fmaf(xv, Wg[(128 + k) * D + j], rg);
    }
    g_Ra[r * D + j] = ra;
    g_Rg[r * D + j] = rg;
}

// ---------------- K3: per-entity GEMM via packed fma.rn.f32x2 ----------------
// C(50000x128) = X @ W; blockIdx.y picks one of 3 weight matrices.
// 128x128 tile / block, 256 threads, 8x8 micro-tile, double-buffered SMEM
// with register-staged global prefetch; ONE barrier per K-step.
__global__ __launch_bounds__(256, 2) void k_ent(const float* __restrict__ X,
                                                const float* __restrict__ Wa,
                                                const float* __restrict__ Wg) {
    __shared__ __align__(16) float Xs[2][16][128];  // [buf][k][m]
    __shared__ __align__(16) float Ws[2][16][128];  // [buf][k][j]
    int tid = threadIdx.x;
    int tx = tid & 15;
    int ty = tid >> 4;
    int m_base = blockIdx.x * 128;
    int w = blockIdx.y;

    const float* Wp = (w == 0) ? Wa : (w == 1) ? (Wa + 128 * D) : Wg;
    float* C = (w == 0) ? g_P1 : (w == 1) ? g_P2 : g_G1;

    // per-thread load coordinates
    int lm  = tid >> 1;               // X row within tile
    int lk4 = (tid & 1) * 8;          // X k offset (8 floats)
    int gm_ld = m_base + lm;
    int wr_r  = tid >> 5;             // W row (0..7)
    int wc4   = (tid & 31) * 4;       // W col (float4)

    unsigned long long acc[2][2][4][2];
    #pragma unroll
    for (int a = 0; a < 2; a++)
        #pragma unroll
        for (int b = 0; b < 2; b++)
            #pragma unroll
            for (int i = 0; i < 4; i++) {
                acc[a][b][i][0] = 0ULL;
                acc[a][b][i][1] = 0ULL;
            }

    float4 xv0, xv1, wv0, wv1;
    // prologue: load tile 0
    {
        xv0 = make_float4(0, 0, 0, 0); xv1 = make_float4(0, 0, 0, 0);
        if (gm_ld < NE) {
            xv0 = *(const float4*)&X[gm_ld * D + lk4];
            xv1 = *(const float4*)&X[gm_ld * D + lk4 + 4];
        }
        wv0 = *(const float4*)&Wp[wr_r * D + wc4];
        wv1 = *(const float4*)&Wp[(wr_r + 8) * D + wc4];
        Xs[0][lk4 + 0][lm] = xv0.x; Xs[0][lk4 + 1][lm] = xv0.y;
        Xs[0][lk4 + 2][lm] = xv0.z; Xs[0][lk4 + 3][lm] = xv0.w;
        Xs[0][lk4 + 4][lm] = xv1.x; Xs[0][lk4 + 5][lm] = xv1.y;
        Xs[0][lk4 + 6][lm] = xv1.z; Xs[0][lk4 + 7][lm] = xv1.w;
        *(float4*)&Ws[0][wr_r][wc4]     = wv0;
        *(float4*)&Ws[0][wr_r + 8][wc4] = wv1;
    }
    __syncthreads();

    #pragma unroll
    for (int it = 0; it < 8; ++it) {
        int buf = it & 1;
        // issue global loads for next tile before computing this one
        if (it < 7) {
            int kb = (it + 1) * 16;
            xv0 = make_float4(0, 0, 0, 0); xv1 = make_float4(0, 0, 0, 0);
            if (gm_ld < NE) {
                xv0 = *(const float4*)&X[gm_ld * D + kb + lk4];
                xv1 = *(const float4*)&X[gm_ld * D + kb + lk4 + 4];
            }
            wv0 = *(const float4*)&Wp[(kb + wr_r) * D + wc4];
            wv1 = *(const float4*)&Wp[(kb + wr_r + 8) * D + wc4];
        }
        #pragma unroll
        for (int kk = 0; kk < 16; ++kk) {
            float4 x0 = *(float4*)&Xs[buf][kk][ty * 4];       // broadcast across tx
            float4 x1 = *(float4*)&Xs[buf][kk][64 + ty * 4];
            ulonglong2 wA = *(const ulonglong2*)&Ws[buf][kk][tx * 4];
            ulonglong2 wB = *(const ulonglong2*)&Ws[buf][kk][64 + tx * 4];

            unsigned long long xd[2][4];
            xd[0][0] = dup2(x0.x); xd[0][1] = dup2(x0.y);
            xd[0][2] = dup2(x0.z); xd[0][3] = dup2(x0.w);
            xd[1][0] = dup2(x1.x); xd[1][1] = dup2(x1.y);
            xd[1][2] = dup2(x1.z); xd[1][3] = dup2(x1.w);

            #pragma unroll
            for (int a = 0; a < 2; a++)
                #pragma unroll
                for (int i = 0; i < 4; i++) {
                    acc[a][0][i][0] = ffma2(xd[a][i], wA.x, acc[a][0][i][0]);
                    acc[a][0][i][1] = ffma2(xd[a][i], wA.y, acc[a][0][i][1]);
                    acc[a][1][i][0] = ffma2(xd[a][i], wB.x, acc[a][1][i][0]);
                    acc[a][1][i][1] = ffma2(xd[a][i], wB.y, acc[a][1][i][1]);
                }
        }
        if (it < 7) {
            int nb = buf ^ 1;
            Xs[nb][lk4 + 0][lm] = xv0.x; Xs[nb][lk4 + 1][lm] = xv0.y;
            Xs[nb][lk4 + 2][lm] = xv0.z; Xs[nb][lk4 + 3][lm] = xv0.w;
            Xs[nb][lk4 + 4][lm] = xv1.x; Xs[nb][lk4 + 5][lm] = xv1.y;
            Xs[nb][lk4 + 6][lm] = xv1.z; Xs[nb][lk4 + 7][lm] = xv1.w;
            *(float4*)&Ws[nb][wr_r][wc4]     = wv0;
            *(float4*)&Ws[nb][wr_r + 8][wc4] = wv1;
        }
        __syncthreads();
    }

    #pragma unroll
    for (int a = 0; a < 2; a++)
        #pragma unroll
        for (int i = 0; i < 4; i++) {
            int gm = m_base + a * 64 + ty * 4 + i;
            if (gm < NE) {
                #pragma unroll
                for (int b = 0; b < 2; b++) {
                    uint2 lo = *reinterpret_cast<uint2*>(&acc[a][b][i][0]);
                    uint2 hi = *reinterpret_cast<uint2*>(&acc[a][b][i][1]);
                    float4 v = make_float4(__uint_as_float(lo.x), __uint_as_float(lo.y),
                                           __uint_as_float(hi.x), __uint_as_float(hi.y));
                    *(float4*)&C[gm * D + b * 64 + tx * 4] = v;
                }
            }
        }
}

// ---------------- K4: exclusive prefix scan of degrees (single block) ------
__global__ void k_scan() {
    __shared__ int s[1024];
    int t = threadIdx.x;
    const int CH = (NE + 1023) / 1024;  // 49
    int base = t * CH;
    int sum = 0;
    for (int i = 0; i < CH; i++)
        if (base + i < NE) sum += g_deg[base + i];
    s[t] = sum;
    __syncthreads();
    for (int o = 1; o < 1024; o <<= 1) {
        int v = (t >= o) ? s[t - o] : 0;
        __syncthreads();
        s[t] += v;
        __syncthreads();
    }
    int run = (t > 0) ? s[t - 1] : 0;
    for (int i = 0; i < CH; i++) {
        if (base + i < NE) {
            g_off[base + i] = run;
            run += g_deg[base + i];
        }
    }
    if (t == 1023) g_off[NE] = s[1023];
}

// ---------------- K5: scatter (head, rel) into CSR ----------------
__global__ void k_scatter(const int* __restrict__ trip) {
    int i = blockIdx.x * blockDim.x + threadIdx.x;
    if (i < NT) {
        int hd = trip[i * 3 + 0];
        int rl = trip[i * 3 + 1];
        int tl = trip[i * 3 + 2];
        int p = atomicAdd(&g_cur[tl], 1);
        g_ehr[g_off[tl] + p] = make_int2(hd, rl);
    }
}

// ---------------- K6: fused attention + softmax + aggregation -------------
// 1 warp per entity. No max-subtraction: |attn_raw| <= sum|av| ~ 1.5, exp safe,
// softmax is shift-invariant so result is identical.
__global__ __launch_bounds__(256) void k_gather(const float* __restrict__ ba,
                                                const float* __restrict__ bg,
                                                const float* __restrict__ av,
                                                float* __restrict__ out) {
    int e = (blockIdx.x * blockDim.x + threadIdx.x) >> 5;
    int lane = threadIdx.x & 31;
    if (e >= NE) return;
    int o0 = g_off[e];
    int deg = g_off[e + 1] - o0;

    int j = lane * 4;
    float4 p1  = *(const float4*)&g_P1[e * D + j];
    float4 bav = *(const float4*)&ba[j];
    float4 av4 = *(const float4*)&av[j];
    float4 bg4 = *(const float4*)&bg[j];
    // p1 + ba precombined
    p1.x += bav.x; p1.y += bav.y; p1.z += bav.z; p1.w += bav.w;

    float ax = 0.f, ay = 0.f, az = 0.f, aw = 0.f;  // weighted msg accum
    float denom = 0.f;
    float sax = 0.f, say = 0.f, saz = 0.f, saw = 0.f;  // sum Ra[rel]
    float sgx = 0.f, sgy = 0.f, sgz = 0.f, sgw = 0.f;  // sum Rg[rel]

    int2 nxt = (deg > 0) ? g_ehr[o0] : make_int2(0, 0);
    for (int jj = 0; jj < deg; ++jj) {
        int2 hr = nxt;
        if (jj + 1 < deg) nxt = g_ehr[o0 + jj + 1];   // prefetch next edge id
        float4 p2 = *(const float4*)&g_P2[hr.x * D + j];
        float4 ra = *(const float4*)&g_Ra[hr.y * D + j];
        float4 g1 = *(const float4*)&g_G1[hr.x * D + j];
        float4 rg = *(const float4*)&g_Rg[hr.y * D + j];

        float s = 0.f;
        s = fmaf(tanh_fast(p1.x + p2.x + ra.x), av4.x, s);
        s = fmaf(tanh_fast(p1.y + p2.y + ra.y), av4.y, s);
        s = fmaf(tanh_fast(p1.z + p2.z + ra.z), av4.z, s);
        s = fmaf(tanh_fast(p1.w + p2.w + ra.w), av4.w, s);
        // reduce within 4-lane head group -> every lane holds its head's score
        s += __shfl_xor_sync(0xffffffffu, s, 1);
        s += __shfl_xor_sync(0xffffffffu, s, 2);
        float ev = __expf(s);

        ax = fmaf(ev, g1.x + rg.x + bg4.x, ax);
        ay = fmaf(ev, g1.y + rg.y + bg4.y, ay);
        az = fmaf(ev, g1.z + rg.z + bg4.z, az);
        aw = fmaf(ev, g1.w + rg.w + bg4.w, aw);
        denom += ev;

        sax += ra.x; say += ra.y; saz += ra.z; saw += ra.w;
        sgx += rg.x; sgy += rg.y; sgz += rg.z; sgw += rg.w;
    }

    // ---- self edge: head = e, rel-feat = mean of Ra/Rg over incoming edges
    {
        float inv = (deg > 0) ? (1.0f / (float)deg) : 0.0f;
        float4 p2 = *(const float4*)&g_P2[e * D + j];
        float4 g1 = *(const float4*)&g_G1[e * D + j];
        float s = 0.f;
        s = fmaf(tanh_fast(p1.x + p2.x + sax * inv), av4.x, s);
        s = fmaf(tanh_fast(p1.y + p2.y + say * inv), av4.y, s);
        s = fmaf(tanh_fast(p1.z + p2.z + saz * inv), av4.z, s);
        s = fmaf(tanh_fast(p1.w + p2.w + saw * inv), av4.w, s);
        s += __shfl_xor_sync(0xffffffffu, s, 1);
        s += __shfl_xor_sync(0xffffffffu, s, 2);
        float ev = __expf(s);
        ax = fmaf(ev, g1.x + sgx * inv + bg4.x, ax);
        ay = fmaf(ev, g1.y + sgy * inv + bg4.y, ay);
        az = fmaf(ev, g1.z + sgz * inv + bg4.z, az);
        aw = fmaf(ev, g1.w + sgw * inv + bg4.w, aw);
        denom += ev;
    }

    float inv = 1.0f / denom;
    *(float4*)&out[e * D + j] = make_float4(ax * inv, ay * inv, az * inv, aw * inv);
}

// ---------------- launch ----------------
extern "C" void kernel_launch(void* const* d_in, const int* in_sizes, int n_in,
                              void* d_out, int out_size) {
    const float* emb_ent = (const float*)d_in[0];
    const float* emb_rel = (const float*)d_in[1];
    const int*   trip    = (const int*)d_in[2];
    const float* Wa      = (const float*)d_in[3];
    const float* ba      = (const float*)d_in[4];
    const float* av      = (const float*)d_in[5];
    const float* Wg      = (const float*)d_in[6];
    const float* bg      = (const float*)d_in[7];
    float* out = (float*)d_out;

    k_zero<<<(NE + 255) / 256, 256>>>();
    k_count<<<(NT + 255) / 256, 256>>>(trip);
    k_rel<<<NRL, 128>>>(emb_rel, Wa, Wg);
    dim3 ent_grid((NE + 127) / 128, 3);
    k_ent<<<ent_grid, 256>>>(emb_ent, Wa, Wg);
    k_scan<<<1, 1024>>>();
    k_scatter<<<(NT + 255) / 256, 256>>>(trip);
    k_gather<<<(NE * 32 + 255) / 256, 256>>>(ba, bg, av, out);
}

// round 5
// speedup vs baseline: 2.5277x; 1.2483x over previous
#include <cuda_runtime.h>

#define NE   50000
#define NRL  64
#define NT   400000
#define D    128
#define NH   8

// ---------------- scratch (device globals; no allocation) ----------------
__device__ float g_P1[NE * D];      // emb_ent @ Wa[0:128] + ba   (tail part)
__device__ float g_P2[NE * D];      // emb_ent @ Wa[128:256]      (head part)
__device__ float g_G1[NE * D];      // emb_ent @ Wg[0:128] + bg   (msg head part)
__device__ float g_Ra[NRL * D];     // emb_rel @ Wa[256:384]
__device__ float g_Rg[NRL * D];     // emb_rel @ Wg[128:256]
__device__ int   g_off[NE + 1];
__device__ int   g_cur[NE];
__device__ int   g_deg[NE];
__device__ int2  g_ehr[NT];         // CSR payload: (head, rel), grouped by tail

// ---------------- helpers ----------------
__device__ __forceinline__ float tanh_fast(float x) {
    float y;
    asm("tanh.approx.f32 %0, %1;" : "=f"(y) : "f"(x));
    return y;
}
__device__ __forceinline__ unsigned long long dup2(float x) {
    unsigned long long r;
    asm("mov.b64 %0, {%1, %1};" : "=l"(r) : "f"(x));
    return r;
}
__device__ __forceinline__ unsigned long long ffma2(unsigned long long a,
                                                    unsigned long long b,
                                                    unsigned long long c) {
    unsigned long long d;
    asm("fma.rn.f32x2 %0, %1, %2, %3;" : "=l"(d) : "l"(a), "l"(b), "l"(c));
    return d;
}

// ---------------- K0: zero deg + cursors ----------------
__global__ void k_zero() {
    int i = blockIdx.x * blockDim.x + threadIdx.x;
    if (i < NE) { g_deg[i] = 0; g_cur[i] = 0; }
}

// ---------------- K1: degree count ----------------
__global__ void k_count(const int* __restrict__ trip) {
    int i = blockIdx.x * blockDim.x + threadIdx.x;
    if (i < NT) atomicAdd(&g_deg[trip[i * 3 + 2]], 1);
}

// ---------------- K2: Ra, Rg (64 x 128 each) ----------------
__global__ void k_rel(const float* __restrict__ emb_rel,
                      const float* __restrict__ Wa,
                      const float* __restrict__ Wg) {
    __shared__ float x[D];
    int r = blockIdx.x;
    int j = threadIdx.x;
    x[j] = emb_rel[r * D + j];
    __syncthreads();
    float ra = 0.0f, rg = 0.0f;
    #pragma unroll 8
    for (int k = 0; k < D; k++) {
        float xv = x[k];
        ra = fmaf(xv, Wa[(256 + k) * D + j], ra);
        rg = fmaf(xv, Wg[(128 + k) * D + j], rg);
    }
    g_Ra[r * D + j] = ra;
    g_Rg[r * D + j] = rg;
}

// ---------------- K3: per-entity GEMM via packed fma.rn.f32x2 ----------------
// C(50000x128) = X @ W; blockIdx.y picks weight matrix (+ bias fold).
// X stored PRE-DUPLICATED in smem so LDS delivers ready f32x2 operands
// (no per-kk dup movs). Double-buffered, one barrier per K-step.
// Dynamic smem: Xs 2*16*256 floats (32KB) + Ws 2*16*128 floats (16KB) = 48KB.
__global__ __launch_bounds__(256, 2) void k_ent(const float* __restrict__ X,
                                                const float* __restrict__ Wa,
                                                const float* __restrict__ Wg,
                                                const float* __restrict__ ba,
                                                const float* __restrict__ bg) {
    extern __shared__ float sm[];
    float (*Xs)[16][256] = (float(*)[16][256])sm;            // [buf][k][2*m dup]
    float (*Ws)[16][128] = (float(*)[16][128])(sm + 8192);   // [buf][k][j]

    int tid = threadIdx.x;
    int tx = tid & 15;
    int ty = tid >> 4;
    int m_base = blockIdx.x * 128;
    int w = blockIdx.y;

    const float* Wp = (w == 0) ? Wa : (w == 1) ? (Wa + 128 * D) : Wg;
    float* C = (w == 0) ? g_P1 : (w == 1) ? g_P2 : g_G1;

    // per-thread load coordinates
    int lm  = tid >> 1;               // X row within tile
    int lk4 = (tid & 1) * 8;          // X k offset (8 floats)
    int gm_ld = m_base + lm;
    int wr_r  = tid >> 5;             // W row (0..7)
    int wc4   = (tid & 31) * 4;       // W col (float4)

    unsigned long long acc[2][2][4][2];
    #pragma unroll
    for (int a = 0; a < 2; a++)
        #pragma unroll
        for (int b = 0; b < 2; b++)
            #pragma unroll
            for (int i = 0; i < 4; i++) {
                acc[a][b][i][0] = 0ULL;
                acc[a][b][i][1] = 0ULL;
            }

    float4 xv0, xv1, wv0, wv1;
    // prologue: load tile 0
    {
        xv0 = make_float4(0, 0, 0, 0); xv1 = make_float4(0, 0, 0, 0);
        if (gm_ld < NE) {
            xv0 = *(const float4*)&X[gm_ld * D + lk4];
            xv1 = *(const float4*)&X[gm_ld * D + lk4 + 4];
        }
        wv0 = *(const float4*)&Wp[wr_r * D + wc4];
        wv1 = *(const float4*)&Wp[(wr_r + 8) * D + wc4];
        *(unsigned long long*)&Xs[0][lk4 + 0][2 * lm] = dup2(xv0.x);
        *(unsigned long long*)&Xs[0][lk4 + 1][2 * lm] = dup2(xv0.y);
        *(unsigned long long*)&Xs[0][lk4 + 2][2 * lm] = dup2(xv0.z);
        *(unsigned long long*)&Xs[0][lk4 + 3][2 * lm] = dup2(xv0.w);
        *(unsigned long long*)&Xs[0][lk4 + 4][2 * lm] = dup2(xv1.x);
        *(unsigned long long*)&Xs[0][lk4 + 5][2 * lm] = dup2(xv1.y);
        *(unsigned long long*)&Xs[0][lk4 + 6][2 * lm] = dup2(xv1.z);
        *(unsigned long long*)&Xs[0][lk4 + 7][2 * lm] = dup2(xv1.w);
        *(float4*)&Ws[0][wr_r][wc4]     = wv0;
        *(float4*)&Ws[0][wr_r + 8][wc4] = wv1;
    }
    __syncthreads();

    #pragma unroll
    for (int it = 0; it < 8; ++it) {
        int buf = it & 1;
        // issue global loads for next tile before computing this one
        if (it < 7) {
            int kb = (it + 1) * 16;
            xv0 = make_float4(0, 0, 0, 0); xv1 = make_float4(0, 0, 0, 0);
            if (gm_ld < NE) {
                xv0 = *(const float4*)&X[gm_ld * D + kb + lk4];
                xv1 = *(const float4*)&X[gm_ld * D + kb + lk4 + 4];
            }
            wv0 = *(const float4*)&Wp[(kb + wr_r) * D + wc4];
            wv1 = *(const float4*)&Wp[(kb + wr_r + 8) * D + wc4];
        }
        #pragma unroll
        for (int kk = 0; kk < 16; ++kk) {
            const ulonglong2* xr = (const ulonglong2*)&Xs[buf][kk][0];
            ulonglong2 xa0 = xr[2 * ty];          // m = 4ty, 4ty+1   (a=0)
            ulonglong2 xa1 = xr[2 * ty + 1];      // m = 4ty+2, 4ty+3
            ulonglong2 xb0 = xr[32 + 2 * ty];     // a=1 half (m+64)
            ulonglong2 xb1 = xr[32 + 2 * ty + 1];
            ulonglong2 wA = *(const ulonglong2*)&Ws[buf][kk][tx * 4];
            ulonglong2 wB = *(const ulonglong2*)&Ws[buf][kk][64 + tx * 4];

            unsigned long long xd[2][4] = {
                { xa0.x, xa0.y, xa1.x, xa1.y },
                { xb0.x, xb0.y, xb1.x, xb1.y }
            };
            #pragma unroll
            for (int a = 0; a < 2; a++)
                #pragma unroll
                for (int i = 0; i < 4; i++) {
                    acc[a][0][i][0] = ffma2(xd[a][i], wA.x, acc[a][0][i][0]);
                    acc[a][0][i][1] = ffma2(xd[a][i], wA.y, acc[a][0][i][1]);
                    acc[a][1][i][0] = ffma2(xd[a][i], wB.x, acc[a][1][i][0]);
                    acc[a][1][i][1] = ffma2(xd[a][i], wB.y, acc[a][1][i][1]);
                }
        }
        if (it < 7) {
            int nb = buf ^ 1;
            *(unsigned long long*)&Xs[nb][lk4 + 0][2 * lm] = dup2(xv0.x);
            *(unsigned long long*)&Xs[nb][lk4 + 1][2 * lm] = dup2(xv0.y);
            *(unsigned long long*)&Xs[nb][lk4 + 2][2 * lm] = dup2(xv0.z);
            *(unsigned long long*)&Xs[nb][lk4 + 3][2 * lm] = dup2(xv0.w);
            *(unsigned long long*)&Xs[nb][lk4 + 4][2 * lm] = dup2(xv1.x);
            *(unsigned long long*)&Xs[nb][lk4 + 5][2 * lm] = dup2(xv1.y);
            *(unsigned long long*)&Xs[nb][lk4 + 6][2 * lm] = dup2(xv1.z);
            *(unsigned long long*)&Xs[nb][lk4 + 7][2 * lm] = dup2(xv1.w);
            *(float4*)&Ws[nb][wr_r][wc4]     = wv0;
            *(float4*)&Ws[nb][wr_r + 8][wc4] = wv1;
        }
        __syncthreads();
    }

    #pragma unroll
    for (int a = 0; a < 2; a++)
        #pragma unroll
        for (int i = 0; i < 4; i++) {
            int gm = m_base + a * 64 + ty * 4 + i;
            if (gm < NE) {
                #pragma unroll
                for (int b = 0; b < 2; b++) {
                    int col = b * 64 + tx * 4;
                    float4 bias = make_float4(0, 0, 0, 0);
                    if (w == 0) bias = *(const float4*)&ba[col];
                    else if (w == 2) bias = *(const float4*)&bg[col];
                    uint2 lo = *reinterpret_cast<uint2*>(&acc[a][b][i][0]);
                    uint2 hi = *reinterpret_cast<uint2*>(&acc[a][b][i][1]);
                    float4 v = make_float4(__uint_as_float(lo.x) + bias.x,
                                           __uint_as_float(lo.y) + bias.y,
                                           __uint_as_float(hi.x) + bias.z,
                                           __uint_as_float(hi.y) + bias.w);
                    *(float4*)&C[gm * D + col] = v;
                }
            }
        }
}

// ---------------- K4: exclusive prefix scan of degrees (single block) ------
__global__ void k_scan() {
    __shared__ int s[1024];
    int t = threadIdx.x;
    const int CH = (NE + 1023) / 1024;  // 49
    int base = t * CH;
    int sum = 0;
    #pragma unroll
    for (int i = 0; i < CH; i++)
        if (base + i < NE) sum += g_deg[base + i];
    s[t] = sum;
    __syncthreads();
    for (int o = 1; o < 1024; o <<= 1) {
        int v = (t >= o) ? s[t - o] : 0;
        __syncthreads();
        s[t] += v;
        __syncthreads();
    }
    int run = (t > 0) ? s[t - 1] : 0;
    #pragma unroll
    for (int i = 0; i < CH; i++) {
        if (base + i < NE) {
            g_off[base + i] = run;
            run += g_deg[base + i];
        }
    }
    if (t == 1023) g_off[NE] = s[1023];
}

// ---------------- K5: scatter (head, rel) into CSR ----------------
__global__ void k_scatter(const int* __restrict__ trip) {
    int i = blockIdx.x * blockDim.x + threadIdx.x;
    if (i < NT) {
        int hd = trip[i * 3 + 0];
        int rl = trip[i * 3 + 1];
        int tl = trip[i * 3 + 2];
        int p = atomicAdd(&g_cur[tl], 1);
        g_ehr[g_off[tl] + p] = make_int2(hd, rl);
    }
}

// ---------------- K6: fused attention + softmax + aggregation -------------
// 1 warp per entity, software-pipelined edge loop.
// ba folded into P1, bg folded into G1 (exact). No max-subtraction:
// |attn_raw| <= sum|av| ~ 1.5, exp safe, softmax shift-invariant.
__global__ __launch_bounds__(256) void k_gather(const float* __restrict__ av,
                                                float* __restrict__ out) {
    int e = (blockIdx.x * blockDim.x + threadIdx.x) >> 5;
    int lane = threadIdx.x & 31;
    if (e >= NE) return;
    int o0 = g_off[e];
    int deg = g_off[e + 1] - o0;

    int j = lane * 4;
    float4 p1  = *(const float4*)&g_P1[e * D + j];   // includes ba
    float4 av4 = *(const float4*)&av[j];

    float ax = 0.f, ay = 0.f, az = 0.f, aw = 0.f;  // weighted msg accum
    float denom = 0.f;
    float sax = 0.f, say = 0.f, saz = 0.f, saw = 0.f;  // sum Ra[rel]
    float sgx = 0.f, sgy = 0.f, sgz = 0.f, sgw = 0.f;  // sum Rg[rel]

    float4 p2c, rac, g1c, rgc;
    if (deg > 0) {
        int2 hr = g_ehr[o0];
        p2c = *(const float4*)&g_P2[hr.x * D + j];
        rac = *(const float4*)&g_Ra[hr.y * D + j];
        g1c = *(const float4*)&g_G1[hr.x * D + j];
        rgc = *(const float4*)&g_Rg[hr.y * D + j];
    }
    for (int jj = 0; jj < deg; ++jj) {
        float4 p2n, ran, g1n, rgn;
        if (jj + 1 < deg) {
            int2 hr = g_ehr[o0 + jj + 1];
            p2n = *(const float4*)&g_P2[hr.x * D + j];
            ran = *(const float4*)&g_Ra[hr.y * D + j];
            g1n = *(const float4*)&g_G1[hr.x * D + j];
            rgn = *(const float4*)&g_Rg[hr.y * D + j];
        }
        float s = 0.f;
        s = fmaf(tanh_fast(p1.x + p2c.x + rac.x), av4.x, s);
        s = fmaf(tanh_fast(p1.y + p2c.y + rac.y), av4.y, s);
        s = fmaf(tanh_fast(p1.z + p2c.z + rac.z), av4.z, s);
        s = fmaf(tanh_fast(p1.w + p2c.w + rac.w), av4.w, s);
        // reduce within 4-lane head group -> every lane holds its head's score
        s += __shfl_xor_sync(0xffffffffu, s, 1);
        s += __shfl_xor_sync(0xffffffffu, s, 2);
        float ev = __expf(s);

        ax = fmaf(ev, g1c.x + rgc.x, ax);   // g1 includes bg
        ay = fmaf(ev, g1c.y + rgc.y, ay);
        az = fmaf(ev, g1c.z + rgc.z, az);
        aw = fmaf(ev, g1c.w + rgc.w, aw);
        denom += ev;

        sax += rac.x; say += rac.y; saz += rac.z; saw += rac.w;
        sgx += rgc.x; sgy += rgc.y; sgz += rgc.z; sgw += rgc.w;

        p2c = p2n; rac = ran; g1c = g1n; rgc = rgn;
    }

    // ---- self edge: head = e, rel-feat = mean of Ra/Rg over incoming edges
    {
        float inv = (deg > 0) ? (1.0f / (float)deg) : 0.0f;
        float4 p2 = *(const float4*)&g_P2[e * D + j];
        float4 g1 = *(const float4*)&g_G1[e * D + j];
        float s = 0.f;
        s = fmaf(tanh_fast(p1.x + p2.x + sax * inv), av4.x, s);
        s = fmaf(tanh_fast(p1.y + p2.y + say * inv), av4.y, s);
        s = fmaf(tanh_fast(p1.z + p2.z + saz * inv), av4.z, s);
        s = fmaf(tanh_fast(p1.w + p2.w + saw * inv), av4.w, s);
        s += __shfl_xor_sync(0xffffffffu, s, 1);
        s += __shfl_xor_sync(0xffffffffu, s, 2);
        float ev = __expf(s);
        ax = fmaf(ev, g1.x + sgx * inv, ax);
        ay = fmaf(ev, g1.y + sgy * inv, ay);
        az = fmaf(ev, g1.z + sgz * inv, az);
        aw = fmaf(ev, g1.w + sgw * inv, aw);
        denom += ev;
    }

    float inv = 1.0f / denom;
    *(float4*)&out[e * D + j] = make_float4(ax * inv, ay * inv, az * inv, aw * inv);
}

// ---------------- launch: fork CSR build onto side stream ----------------
extern "C" void kernel_launch(void* const* d_in, const int* in_sizes, int n_in,
                              void* d_out, int out_size) {
    const float* emb_ent = (const float*)d_in[0];
    const float* emb_rel = (const float*)d_in[1];
    const int*   trip    = (const int*)d_in[2];
    const float* Wa      = (const float*)d_in[3];
    const float* ba      = (const float*)d_in[4];
    const float* av      = (const float*)d_in[5];
    const float* Wg      = (const float*)d_in[6];
    const float* bg      = (const float*)d_in[7];
    float* out = (float*)d_out;

    static cudaStream_t s2 = nullptr;
    static cudaEvent_t evF = nullptr, evJ = nullptr;
    if (s2 == nullptr) {   // one-time setup (first call is the uncaptured correctness run)
        cudaStreamCreateWithFlags(&s2, cudaStreamNonBlocking);
        cudaEventCreateWithFlags(&evF, cudaEventDisableTiming);
        cudaEventCreateWithFlags(&evJ, cudaEventDisableTiming);
        cudaFuncSetAttribute(k_ent, cudaFuncAttributeMaxDynamicSharedMemorySize, 49152);
    }

    // fork: CSR build chain on side stream
    cudaEventRecord(evF, 0);
    cudaStreamWaitEvent(s2, evF, 0);
    k_zero<<<(NE + 255) / 256, 256, 0, s2>>>();
    k_count<<<(NT + 255) / 256, 256, 0, s2>>>(trip);
    k_scan<<<1, 1024, 0, s2>>>();
    k_scatter<<<(NT + 255) / 256, 256, 0, s2>>>(trip);
    cudaEventRecord(evJ, s2);

    // main stream: GEMM chain
    k_rel<<<NRL, 128>>>(emb_rel, Wa, Wg);
    dim3 ent_grid((NE + 127) / 128, 3);
    k_ent<<<ent_grid, 256, 49152>>>(emb_ent, Wa, Wg, ba, bg);

    // join, then fused gather
    cudaStreamWaitEvent(0, evJ, 0);
    k_gather<<<(NE * 32 + 255) / 256, 256>>>(av, out);
}